// round 15
// baseline (speedup 1.0000x reference)
#include <cuda_runtime.h>
#include <cuda_fp16.h>
#include <cstdint>
#include <cstddef>

#define BATCH 2048
#define SN 64         // S
#define EN 256        // E
#define EN2 264       // padded smem row (conflict-free att)
#define DN 512        // D
#define INN 32        // IN
#define TN 64         // T
#define KA 544        // D + IN
#define N4D 2048      // 4*D (gate cols, interleaved n=4d+g)
#define NF 2816       // fused weight cols: 2048 gates | 512 p | 256 u
#define NB 768        // p|u cols
#define SEQLEN 128    // 31 hist + 64 cur + pad

#define BN 128
#define BK 32
#define BM2 64
#define DYN2 (3 * ((BM2 * (BK + 8)) + (BK * (BN + 8))) * 2)   // 41472 B
#define BM 128
#define DYN_I (3 * ((BM * (BK + 8)) + (BK * (BN + 8))) * 2)

// ---------------- scratch (__device__ globals; no allocation) ----------------
__device__ __align__(16) __half g_enc[(size_t)BATCH * SN * EN];    // fp16 encoder
__device__ __align__(16) __half g_Xcat[3][(size_t)BATCH * KA];     // [h fp16 | x fp16]
__device__ __align__(16) float  g_c[(size_t)BATCH * DN];           // LSTM cell state
__device__ __align__(16) float  g_gates[(size_t)BATCH * N4D];      // init GEMM output only
__device__ __align__(16) float  g_Pall[(size_t)TN * BATCH * NB];   // p,u per step (fp32)
__device__ __align__(16) __half g_Hall[(size_t)TN * BATCH * DN];   // h per step (fp16)
__device__ __align__(16) __half g_WfT[(size_t)KA * NF];            // fused weights [K][N]
__device__ __align__(16) __half g_WiT[(size_t)288 * 1024];         // init weights [K][N]
__device__ __align__(16) __half g_Inp[(size_t)BATCH * 288];        // [mean_enc | speed0]
__device__ __align__(16) float  g_gb[N4D];                         // (b_ih+b_hh) interleaved
__device__ __align__(16) float  g_seq[(size_t)BATCH * SEQLEN];     // speed sequence

// ---------------- helpers ----------------
__device__ __forceinline__ uint32_t smem_u32(const void* p) {
    return (uint32_t)__cvta_generic_to_shared(p);
}
__device__ __forceinline__ void cp16(uint32_t dst, const void* src) {
    asm volatile("cp.async.cg.shared.global [%0], [%1], 16;\n" :: "r"(dst), "l"(src));
}

// ---------------- fused per-step kernel (BM=64, 128 threads, occ 5 => ONE WAVE) ----------------
// 704 CTAs: blk [0,192) = pu tiles (bx 16..21), blk [192,704) = gate tiles (bx 0..15).
// Reads Xcat[t%3] = (h_{t-1} | x_t).
// Gates (t<TN): LSTM epilogue -> Xcat[(t+1)%3], g_c, g_Hall[t].
// pu (t>=1):   pu(h_{t-1}) -> g_Pall[t-1].
__global__ __launch_bounds__(128, 5) void fused_step(int t) {
    extern __shared__ char dynsmem[];
    const int blk = blockIdx.x;
    const int tid = threadIdx.x;
    if (blk >= 192 && t == TN) return;     // no gates on tail
    if (blk < 192 && t == 0) return;       // pu(h_init) unused

    int bx, by;
    if (blk < 192) { by = blk / 6; bx = 16 + blk % 6; }
    else           { int g = blk - 192; by = g >> 4; bx = g & 15; }
    const int bm = by * BM2;
    const int bn = bx * BN;
    const bool is_gate = (bx < 16);

    const __half* Ain = g_Xcat[t % 3];
    __half* Xout      = g_Xcat[(t + 1) % 3];

    auto As = (__half (*)[BM2][BK + 8])dynsmem;
    auto Bs = (__half (*)[BK][BN + 8])(dynsmem + 3 * BM2 * (BK + 8) * 2);

    const int lane = tid & 31;
    const int warp = tid >> 5;
    const int wm   = warp & 1;     // 2 M-warps of 32 rows
    const int wn   = warp >> 1;    // 2 N-warps of 64 cols

    float acc[2][8][4];
#pragma unroll
    for (int a = 0; a < 2; a++)
#pragma unroll
        for (int b = 0; b < 8; b++)
#pragma unroll
            for (int c = 0; c < 4; c++) acc[a][b][c] = 0.f;

    auto load_async = [&](int kt, int buf) {
        const int k0 = kt * BK;
        // A tile 64x32: 256 16B chunks, 2 per thread
#pragma unroll
        for (int i = 0; i < 2; i++) {
            int idx = tid + i * 128;
            int row = idx >> 2, q = idx & 3;
            cp16(smem_u32(&As[buf][row][q * 8]),
                 Ain + (size_t)(bm + row) * KA + k0 + q * 8);
        }
        // B tile 32x128: 512 chunks, 4 per thread
#pragma unroll
        for (int i = 0; i < 4; i++) {
            int idx = tid + i * 128;
            int row = idx >> 4, q = idx & 15;
            cp16(smem_u32(&Bs[buf][row][q * 8]),
                 g_WfT + (size_t)(k0 + row) * NF + bn + q * 8);
        }
        asm volatile("cp.async.commit_group;\n");
    };

    constexpr int KT = KA / BK;   // 17
    load_async(0, 0);
    load_async(1, 1);

    for (int kt = 0; kt < KT; kt++) {
        if (kt + 1 < KT) asm volatile("cp.async.wait_group 1;\n");
        else             asm volatile("cp.async.wait_group 0;\n");
        __syncthreads();
        if (kt + 2 < KT) load_async(kt + 2, (kt + 2) % 3);
        const int buf = kt % 3;

#pragma unroll
        for (int kk = 0; kk < 2; kk++) {
            uint32_t af[2][4], bf[8][2];
#pragma unroll
            for (int im = 0; im < 2; im++) {
                uint32_t addr = smem_u32(
                    &As[buf][wm * 32 + im * 16 + (lane & 15)][kk * 16 + (lane >> 4) * 8]);
                asm volatile("ldmatrix.sync.aligned.m8n8.x4.shared.b16 {%0,%1,%2,%3}, [%4];\n"
                             : "=r"(af[im][0]), "=r"(af[im][1]), "=r"(af[im][2]), "=r"(af[im][3])
                             : "r"(addr));
            }
#pragma unroll
            for (int in = 0; in < 8; in++) {
                uint32_t addr = smem_u32(&Bs[buf][kk * 16 + (lane & 15)][wn * 64 + in * 8]);
                asm volatile("ldmatrix.sync.aligned.m8n8.x2.trans.shared.b16 {%0,%1}, [%2];\n"
                             : "=r"(bf[in][0]), "=r"(bf[in][1])
                             : "r"(addr));
            }
#pragma unroll
            for (int im = 0; im < 2; im++)
#pragma unroll
                for (int in = 0; in < 8; in++)
                    asm volatile("mma.sync.aligned.m16n8k16.row.col.f32.f16.f16.f32 "
                                 "{%0,%1,%2,%3}, {%4,%5,%6,%7}, {%8,%9}, {%0,%1,%2,%3};\n"
                                 : "+f"(acc[im][in][0]), "+f"(acc[im][in][1]),
                                   "+f"(acc[im][in][2]), "+f"(acc[im][in][3])
                                 : "r"(af[im][0]), "r"(af[im][1]), "r"(af[im][2]), "r"(af[im][3]),
                                   "r"(bf[in][0]), "r"(bf[in][1]));
        }
    }

    if (is_gate) {
        // ---- LSTM epilogue, staged through smem for coalesced gmem ----
        float*  sC = (float*)dynsmem;                    // [64][36] c in/out
        __half* sH = (__half*)(dynsmem + 64 * 36 * 4);   // [64][40] h2
        const int d0 = bn >> 2;                          // 32 consecutive d

        __syncthreads();
#pragma unroll
        for (int k = 0; k < 4; k++) {
            int idx = tid + k * 128;
            int row = idx >> 3, q = idx & 7;
            ((float4*)sC)[row * 9 + q] =
                *(const float4*)(g_c + (size_t)(bm + row) * DN + d0 + q * 4);
        }
        __syncthreads();

        const int pair_sel = lane & 1;
#pragma unroll
        for (int im = 0; im < 2; im++) {
            const int rl = wm * 32 + im * 16 + (lane >> 2);
#pragma unroll
            for (int in = 0; in < 8; in++) {
                const int ccg = bn + wn * 64 + in * 8 + (lane & 3) * 2;
                float b0 = __ldg(&g_gb[ccg]);
                float b1 = __ldg(&g_gb[ccg + 1]);
                float a0 = acc[im][in][0] + b0;
                float a1 = acc[im][in][1] + b1;
                float a2 = acc[im][in][2] + b0;
                float a3 = acc[im][in][3] + b1;
                float o0 = __shfl_xor_sync(0xffffffffu, a0, 1);
                float o1 = __shfl_xor_sync(0xffffffffu, a1, 1);
                float o2 = __shfl_xor_sync(0xffffffffu, a2, 1);
                float o3 = __shfl_xor_sync(0xffffffffu, a3, 1);
                int row_l; float xi, xf, xg, xo;
                if (pair_sel == 0) { row_l = rl;     xi = a0; xf = a1; xg = o0; xo = o1; }
                else               { row_l = rl + 8; xi = o2; xf = o3; xg = a2; xo = a3; }
                const int d_l = wn * 16 + in * 2 + ((lane & 3) >> 1);
                float si = 1.f / (1.f + expf(-xi));
                float sf = 1.f / (1.f + expf(-xf));
                float so = 1.f / (1.f + expf(-xo));
                float c2 = sf * sC[row_l * 36 + d_l] + si * tanhf(xg);
                float h2 = so * tanhf(c2);
                sC[row_l * 36 + d_l] = c2;
                sH[row_l * 40 + d_l] = __float2half(h2);
            }
        }
        __syncthreads();

#pragma unroll
        for (int k = 0; k < 4; k++) {
            int idx = tid + k * 128;
            int row = idx >> 3, q = idx & 7;
            *(float4*)(g_c + (size_t)(bm + row) * DN + d0 + q * 4) =
                ((const float4*)sC)[row * 9 + q];
        }
#pragma unroll
        for (int k = 0; k < 2; k++) {
            int idx = tid + k * 128;          // 0..255 uint4 chunks
            int row = idx >> 2, q = idx & 3;
            uint4 v = ((const uint4*)sH)[row * 5 + q];
            *(uint4*)(Xout + (size_t)(bm + row) * KA + d0 + q * 8) = v;
            *(uint4*)(g_Hall + ((size_t)t * BATCH + bm + row) * DN + d0 + q * 8) = v;
        }
        if (bx == 0) {
            const int rr = bm + (tid >> 1);
            const int jb = (tid & 1) * 16;
#pragma unroll
            for (int j = 0; j < 16; j++) {
                int jj = jb + j;
                Xout[(size_t)rr * KA + DN + jj] =
                    __float2half(g_seq[(size_t)rr * SEQLEN + t + 1 + jj]);
            }
        }
    } else {
        // ---- pu(h_{t-1}) -> Pall[t-1] ----
        float* PoutW = g_Pall + (size_t)(t - 1) * BATCH * NB;
#pragma unroll
        for (int im = 0; im < 2; im++) {
            const int r = bm + wm * 32 + im * 16 + (lane >> 2);
#pragma unroll
            for (int in = 0; in < 8; in++) {
                const int cc = bn - N4D + wn * 64 + in * 8 + (lane & 3) * 2;
                *(float2*)(PoutW + (size_t)r * NB + cc) =
                    make_float2(acc[im][in][0], acc[im][in][1]);
                *(float2*)(PoutW + (size_t)(r + 8) * NB + cc) =
                    make_float2(acc[im][in][2], acc[im][in][3]);
            }
        }
    }
}

// ---------------- deferred attention: all 64 steps, enc loaded ONCE ----------------
__global__ __launch_bounds__(256) void attn_all(
    const float* __restrict__ b_wp, const float* __restrict__ W_vp,
    const float* __restrict__ b_vp, const float* __restrict__ W_fc,
    const float* __restrict__ b_fc,
    float* __restrict__ outPred, float* __restrict__ outAlpha)
{
    const int b  = blockIdx.x;
    const int tid = threadIdx.x;

    __shared__ __align__(16) __half sEnc[SN * EN2];   // 33.8 KB
    __shared__ float sBwp[DN];
    __shared__ float sWvp[DN];
    __shared__ float sWfc[NB];
    __shared__ float sU[EN];
    __shared__ float sAtt[SN];
    __shared__ float sAlpha[SN];
    __shared__ float sRed[8];
    __shared__ float sAligned;

    const uint4* ge = (const uint4*)(g_enc + (size_t)b * SN * EN);
#pragma unroll
    for (int i = 0; i < 8; i++) {
        int c = tid + i * 256;
        int row = c >> 5, jc = c & 31;
        cp16(smem_u32(sEnc + row * EN2 + jc * 8), ge + c);
    }
    asm volatile("cp.async.commit_group;\n");

    sBwp[tid] = b_wp[tid];       sBwp[tid + 256] = b_wp[tid + 256];
    sWvp[tid] = W_vp[tid];       sWvp[tid + 256] = W_vp[tid + 256];
    sWfc[tid] = W_fc[tid];       sWfc[tid + 256] = W_fc[tid + 256];
    sWfc[tid + 512] = W_fc[tid + 512];
    const float bvp0 = b_vp[0];
    const float bfc0 = b_fc[0];

    asm volatile("cp.async.wait_group 0;\n");
    __syncthreads();

    for (int tt = 0; tt < TN; tt++) {
        const float*  Pr = g_Pall + ((size_t)tt * BATCH + b) * NB;
        const __half* hr = g_Hall + ((size_t)tt * BATCH + b) * DN;

        sU[tid] = Pr[DN + tid];

        float part = tanhf(Pr[tid] + sBwp[tid]) * sWvp[tid]
                   + tanhf(Pr[tid + 256] + sBwp[tid + 256]) * sWvp[tid + 256];
#pragma unroll
        for (int o = 16; o; o >>= 1) part += __shfl_xor_sync(0xffffffffu, part, o);
        if ((tid & 31) == 0) sRed[tid >> 5] = part;
        __syncthreads();
        if (tid == 0) {
            float tot = 0.f;
#pragma unroll
            for (int i = 0; i < 8; i++) tot += sRed[i];
            tot += bvp0;
            sAligned = (float)SN / (1.f + expf(-tot));
        }
        __syncthreads();
        const float aligned = sAligned;

        {
            int s = tid >> 2, q = tid & 3;
            const __half* er = sEnc + s * EN2;
            float a = 0.f;
#pragma unroll 16
            for (int e = q; e < EN; e += 4) a += __half2float(er[e]) * sU[e];
            a += __shfl_xor_sync(0xffffffffu, a, 1);
            a += __shfl_xor_sync(0xffffffffu, a, 2);
            if (q == 0) sAtt[s] = a;
        }
        __syncthreads();

        if (tid < 32) {
            float a0 = sAtt[tid], a1 = sAtt[tid + 32];
            float m = fmaxf(a0, a1);
#pragma unroll
            for (int o = 16; o; o >>= 1) m = fmaxf(m, __shfl_xor_sync(0xffffffffu, m, o));
            float e0 = expf(a0 - m), e1 = expf(a1 - m);
            float s2 = e0 + e1;
#pragma unroll
            for (int o = 16; o; o >>= 1) s2 += __shfl_xor_sync(0xffffffffu, s2, o);
            float inv = 1.f / s2;
            float d0 = (float)tid - aligned, d1 = (float)(tid + 32) - aligned;
            sAlpha[tid]      = e0 * inv * expf(-0.5f * d0 * d0);
            sAlpha[tid + 32] = e1 * inv * expf(-0.5f * d1 * d1);
        }
        __syncthreads();

        if (tid < SN)
            outAlpha[((size_t)b * TN + tt) * SN + tid] = sAlpha[tid];

        float awe = 0.f;
#pragma unroll 16
        for (int s = 0; s < SN; s++) awe += __half2float(sEnc[s * EN2 + tid]) * sAlpha[s];

        float pp = awe * sWfc[tid]
                 + __half2float(hr[tid])       * sWfc[EN + tid]
                 + __half2float(hr[tid + 256]) * sWfc[EN + 256 + tid];
#pragma unroll
        for (int o = 16; o; o >>= 1) pp += __shfl_xor_sync(0xffffffffu, pp, o);
        if ((tid & 31) == 0) sRed[tid >> 5] = pp;
        __syncthreads();
        if (tid == 0) {
            float tot = 0.f;
#pragma unroll
            for (int i = 0; i < 8; i++) tot += sRed[i];
            outPred[(size_t)b * TN + tt] = tot + bfc0;
        }
        __syncthreads();
    }
}

// ---------------- 256-thread mainloop (init GEMM only) ----------------
template<int K, int LDA, int LDB>
__device__ __forceinline__ void gemm_mainloop(const __half* __restrict__ A,
                                              const __half* __restrict__ Bt,
                                              int bm, int bn,
                                              float acc[4][4][4],
                                              char* dynsmem)
{
    auto As = (__half (*)[BM][BK + 8])dynsmem;
    auto Bs = (__half (*)[BK][BN + 8])(dynsmem + 3 * BM * (BK + 8) * 2);

    const int tid  = threadIdx.x;
    const int lane = tid & 31;
    const int warp = tid >> 5;
    const int wm   = warp & 1;
    const int wn   = warp >> 1;

#pragma unroll
    for (int a = 0; a < 4; a++)
#pragma unroll
        for (int b = 0; b < 4; b++)
#pragma unroll
            for (int c = 0; c < 4; c++) acc[a][b][c] = 0.f;

    const int am  = tid >> 2;
    const int akq = tid & 3;
    const int bk  = tid >> 4;
    const int bnq = tid & 15;

    auto load_async = [&](int kt, int buf) {
        const int k0 = kt * BK;
        cp16(smem_u32(&As[buf][am][akq * 8]),
             A + (size_t)(bm + am) * LDA + k0 + akq * 8);
        cp16(smem_u32(&As[buf][am + 64][akq * 8]),
             A + (size_t)(bm + am + 64) * LDA + k0 + akq * 8);
        cp16(smem_u32(&Bs[buf][bk][bnq * 8]),
             Bt + (size_t)(k0 + bk) * LDB + bn + bnq * 8);
        cp16(smem_u32(&Bs[buf][bk + 16][bnq * 8]),
             Bt + (size_t)(k0 + bk + 16) * LDB + bn + bnq * 8);
        asm volatile("cp.async.commit_group;\n");
    };

    constexpr int KT = K / BK;
    load_async(0, 0);
    load_async(1, 1);

    for (int kt = 0; kt < KT; kt++) {
        if (kt + 1 < KT) asm volatile("cp.async.wait_group 1;\n");
        else             asm volatile("cp.async.wait_group 0;\n");
        __syncthreads();
        if (kt + 2 < KT) load_async(kt + 2, (kt + 2) % 3);
        const int buf = kt % 3;

#pragma unroll
        for (int kk = 0; kk < 2; kk++) {
            uint32_t af[4][4], bf[4][2];
#pragma unroll
            for (int im = 0; im < 4; im++) {
                uint32_t addr = smem_u32(
                    &As[buf][wm * 64 + im * 16 + (lane & 15)][kk * 16 + (lane >> 4) * 8]);
                asm volatile("ldmatrix.sync.aligned.m8n8.x4.shared.b16 {%0,%1,%2,%3}, [%4];\n"
                             : "=r"(af[im][0]), "=r"(af[im][1]), "=r"(af[im][2]), "=r"(af[im][3])
                             : "r"(addr));
            }
#pragma unroll
            for (int in = 0; in < 4; in++) {
                uint32_t addr = smem_u32(&Bs[buf][kk * 16 + (lane & 15)][wn * 32 + in * 8]);
                asm volatile("ldmatrix.sync.aligned.m8n8.x2.trans.shared.b16 {%0,%1}, [%2];\n"
                             : "=r"(bf[in][0]), "=r"(bf[in][1])
                             : "r"(addr));
            }
#pragma unroll
            for (int im = 0; im < 4; im++)
#pragma unroll
                for (int in = 0; in < 4; in++)
                    asm volatile("mma.sync.aligned.m16n8k16.row.col.f32.f16.f16.f32 "
                                 "{%0,%1,%2,%3}, {%4,%5,%6,%7}, {%8,%9}, {%0,%1,%2,%3};\n"
                                 : "+f"(acc[im][in][0]), "+f"(acc[im][in][1]),
                                   "+f"(acc[im][in][2]), "+f"(acc[im][in][3])
                                 : "r"(af[im][0]), "r"(af[im][1]), "r"(af[im][2]), "r"(af[im][3]),
                                   "r"(bf[in][0]), "r"(bf[in][1]));
        }
    }
}

__global__ __launch_bounds__(256, 2) void gemmI_kernel() {
    extern __shared__ char dynsmem[];
    float acc[4][4][4];
    const int bm = blockIdx.y * BM;
    const int bn = blockIdx.x * BN;
    gemm_mainloop<288, 288, 1024>(g_Inp, g_WiT, bm, bn, acc, dynsmem);
    const int tid  = threadIdx.x;
    const int lane = tid & 31;
    const int warp = tid >> 5;
    const int wm   = warp & 1;
    const int wn   = warp >> 1;
#pragma unroll
    for (int im = 0; im < 4; im++) {
        const int r = bm + wm * 64 + im * 16 + (lane >> 2);
#pragma unroll
        for (int in = 0; in < 4; in++) {
            const int cc = bn + wn * 32 + in * 8 + (lane & 3) * 2;
            *(float2*)(g_gates + (size_t)r * 1024 + cc) =
                make_float2(acc[im][in][0], acc[im][in][1]);
            *(float2*)(g_gates + (size_t)(r + 8) * 1024 + cc) =
                make_float2(acc[im][in][2], acc[im][in][3]);
        }
    }
}

// ---------------- merged init / pack kernels ----------------
__global__ void prep1(const float* __restrict__ encSrc,
                      const float* __restrict__ hist, const float* __restrict__ cur) {
    size_t i = (size_t)blockIdx.x * 256 + threadIdx.x;
    const size_t n4 = (size_t)BATCH * SN * EN / 4;
    if (i < n4) {
        float4 v = ((const float4*)encSrc)[i];
        __half2* dst = (__half2*)g_enc;
        dst[2 * i]     = __floats2half2_rn(v.x, v.y);
        dst[2 * i + 1] = __floats2half2_rn(v.z, v.w);
    }
    if (i < (size_t)BATCH * SEQLEN) {
        int b = (int)(i / SEQLEN), j = (int)(i - (size_t)b * SEQLEN);
        float v = (j < 31) ? hist[(size_t)b * 31 + j]
                : (j < 95) ? cur[(size_t)b * TN + (j - 31)] : 0.f;
        g_seq[i] = v;
    }
}
__global__ void prep2(const float* __restrict__ W_hh, const float* __restrict__ W_ih,
                      const float* __restrict__ W_wp, const float* __restrict__ W_wa,
                      const float* __restrict__ b_ih, const float* __restrict__ b_hh,
                      const float* __restrict__ W_init_h, const float* __restrict__ W_init_c) {
    int idx = blockIdx.x * 256 + threadIdx.x;
    if (idx < N4D) {
        int d = idx >> 2, g = idx & 3;
        g_gb[idx] = b_ih[g * DN + d] + b_hh[g * DN + d];
    }
    if (idx < 288 * 1024) {
        int k = idx / 1024, n = idx - k * 1024;
        float v = (n < DN) ? W_init_h[(size_t)n * 288 + k]
                           : W_init_c[(size_t)(n - DN) * 288 + k];
        g_WiT[idx] = __float2half(v);
    }
    if (idx >= KA * NF) return;
    int k = idx / NF, n = idx - k * NF;
    float v;
    if (n < N4D) {
        int d = n >> 2, g = n & 3;
        int gr = g * DN + d;
        v = (k < DN) ? W_hh[(size_t)gr * DN + k] : W_ih[(size_t)gr * INN + (k - DN)];
    } else if (n < N4D + DN) {
        int d = n - N4D;
        v = (k < DN) ? W_wp[(size_t)d * DN + k] : 0.f;
    } else {
        int e = n - N4D - DN;
        v = (k < DN) ? W_wa[(size_t)k * EN + e] : 0.f;
    }
    g_WfT[idx] = __float2half(v);
}
__global__ void mean_inp(const float* __restrict__ cEnc) {
    int b = blockIdx.x, tid = threadIdx.x;
    const float* p = cEnc + (size_t)b * SN * EN + tid;
    float s = 0.f;
#pragma unroll 8
    for (int i = 0; i < SN; i++) s += p[(size_t)i * EN];
    g_Inp[(size_t)b * 288 + tid] = __float2half(s * (1.f / 64.f));
    if (tid < INN)
        g_Inp[(size_t)b * 288 + EN + tid] = __float2half(g_seq[(size_t)b * SEQLEN + tid]);
}
__global__ void init_finish(const float* __restrict__ b_init_h, const float* __restrict__ b_init_c) {
    int idx = blockIdx.x * 256 + threadIdx.x;
    if (idx >= BATCH * KA) return;
    int b = idx / KA, d = idx - b * KA;
    if (d < DN) {
        float h0 = g_gates[(size_t)b * 1024 + d] + b_init_h[d];
        float c0 = g_gates[(size_t)b * 1024 + DN + d] + b_init_c[d];
        g_c[(size_t)b * DN + d] = c0;
        g_Xcat[0][idx] = __float2half(h0);
    } else {
        g_Xcat[0][idx] = __float2half(g_seq[(size_t)b * SEQLEN + (d - DN)]);  // x_0
    }
}

// ---------------- launcher (single stream, graph-capturable) ----------------
extern "C" void kernel_launch(void* const* d_in, const int* in_sizes, int n_in,
                              void* d_out, int out_size) {
    const float* cEnc       = (const float*)d_in[0];
    const float* curSpeeds  = (const float*)d_in[1];
    const float* histSpeeds = (const float*)d_in[2];
    int wo = (n_in > 5 && in_sizes[5] == 1) ? 6 : 5;
    const float* W_init_h = (const float*)d_in[wo + 0];
    const float* b_init_h = (const float*)d_in[wo + 1];
    const float* W_init_c = (const float*)d_in[wo + 2];
    const float* b_init_c = (const float*)d_in[wo + 3];
    const float* W_ih     = (const float*)d_in[wo + 4];
    const float* W_hh     = (const float*)d_in[wo + 5];
    const float* b_ih     = (const float*)d_in[wo + 6];
    const float* b_hh     = (const float*)d_in[wo + 7];
    const float* W_wa     = (const float*)d_in[wo + 8];
    // b_wa (wo+9) is softmax-invariant: unused
    const float* W_wp     = (const float*)d_in[wo + 10];
    const float* b_wp     = (const float*)d_in[wo + 11];
    const float* W_vp     = (const float*)d_in[wo + 12];
    const float* b_vp     = (const float*)d_in[wo + 13];
    const float* W_fc     = (const float*)d_in[wo + 14];
    const float* b_fc     = (const float*)d_in[wo + 15];

    float* outPred  = (float*)d_out;                 // [B,T,1]
    float* outAlpha = outPred + (size_t)BATCH * TN;  // [B,T,S]

    cudaFuncSetAttribute(fused_step, cudaFuncAttributeMaxDynamicSharedMemorySize, DYN2);
    cudaFuncSetAttribute(gemmI_kernel, cudaFuncAttributeMaxDynamicSharedMemorySize, DYN_I);

    prep1<<<32768, 256>>>(cEnc, histSpeeds, curSpeeds);
    prep2<<<(KA * NF + 255) / 256, 256>>>(W_hh, W_ih, W_wp, W_wa,
                                          b_ih, b_hh, W_init_h, W_init_c);
    mean_inp<<<BATCH, 256>>>(cEnc);
    gemmI_kernel<<<dim3(1024 / BN, BATCH / BM), 256, DYN_I>>>();
    init_finish<<<(BATCH * KA) / 256, 256>>>(b_init_h, b_init_c);

    // gemm chain back-to-back; 704 CTAs at occupancy 5 = ONE resident wave
    for (int t = 0; t <= TN; t++)
        fused_step<<<704, 128, DYN2>>>(t);

    // all 64 attention steps in one pass (enc loaded once per batch)
    attn_all<<<BATCH, 256>>>(b_wp, W_vp, b_vp, W_fc, b_fc, outPred, outAlpha);
}

// round 16
// speedup vs baseline: 1.0331x; 1.0331x over previous
#include <cuda_runtime.h>
#include <cuda_fp16.h>
#include <cstdint>
#include <cstddef>

#define BATCH 2048
#define SN 64         // S
#define EN 256        // E
#define EN2 264       // padded smem row (conflict-free att)
#define DN 512        // D
#define INN 32        // IN
#define TN 64         // T
#define KA 544        // D + IN
#define N4D 2048      // 4*D (gate cols, interleaved n=4d+g)
#define NF 2816       // fused weight cols: 2048 gates | 512 p | 256 u
#define NB 768        // p|u cols
#define SEQLEN 128    // 31 hist + 64 cur + pad

#define BM 128
#define BN 128
#define BK 32
#define DYN_I (3 * ((BM * (BK + 8)) + (BK * (BN + 8))) * 2)   // 56832 B

// ---------------- scratch (__device__ globals; no allocation) ----------------
__device__ __align__(16) __half g_enc[(size_t)BATCH * SN * EN];    // fp16 encoder
__device__ __align__(16) __half g_Xcat[2][(size_t)BATCH * KA];     // [h fp16 | x fp16]
__device__ __align__(16) float  g_c[(size_t)BATCH * DN];           // LSTM cell state
__device__ __align__(16) float  g_gates[(size_t)BATCH * N4D];      // init GEMM output only
__device__ __align__(16) float  g_Pall[(size_t)TN * BATCH * NB];   // p,u per step (fp32)
__device__ __align__(16) __half g_Hall[(size_t)TN * BATCH * DN];   // h per step (fp16)
__device__ __align__(16) __half g_WfT[(size_t)KA * NF];            // fused weights [K][N]
__device__ __align__(16) __half g_WiT[(size_t)288 * 1024];         // init weights [K][N]
__device__ __align__(16) __half g_Inp[(size_t)BATCH * 288];        // [mean_enc | speed0]
__device__ __align__(16) float  g_gb[N4D];                         // (b_ih+b_hh) interleaved
__device__ __align__(16) float  g_seq[(size_t)BATCH * SEQLEN];     // speed sequence

// ---------------- helpers ----------------
__device__ __forceinline__ uint32_t smem_u32(const void* p) {
    return (uint32_t)__cvta_generic_to_shared(p);
}
__device__ __forceinline__ void cp16(uint32_t dst, const void* src) {
    asm volatile("cp.async.cg.shared.global [%0], [%1], 16;\n" :: "r"(dst), "l"(src));
}

// ---------------- 256-thread BM=128 mainloop (proven fastest per-SM config) ----------------
// 3-stage cp.async, one barrier per k-tile; no trailing sync (caller syncs before smem reuse).
template<int K, int LDA, int LDB>
__device__ __forceinline__ void gemm_mainloop(const __half* __restrict__ A,
                                              const __half* __restrict__ Bt,
                                              int bm, int bn,
                                              float acc[4][4][4],
                                              char* dynsmem)
{
    auto As = (__half (*)[BM][BK + 8])dynsmem;
    auto Bs = (__half (*)[BK][BN + 8])(dynsmem + 3 * BM * (BK + 8) * 2);

    const int tid  = threadIdx.x;
    const int lane = tid & 31;
    const int warp = tid >> 5;
    const int wm   = warp & 1;
    const int wn   = warp >> 1;

#pragma unroll
    for (int a = 0; a < 4; a++)
#pragma unroll
        for (int b = 0; b < 4; b++)
#pragma unroll
            for (int c = 0; c < 4; c++) acc[a][b][c] = 0.f;

    const int am  = tid >> 2;
    const int akq = tid & 3;
    const int bk  = tid >> 4;
    const int bnq = tid & 15;

    auto load_async = [&](int kt, int buf) {
        const int k0 = kt * BK;
        cp16(smem_u32(&As[buf][am][akq * 8]),
             A + (size_t)(bm + am) * LDA + k0 + akq * 8);
        cp16(smem_u32(&As[buf][am + 64][akq * 8]),
             A + (size_t)(bm + am + 64) * LDA + k0 + akq * 8);
        cp16(smem_u32(&Bs[buf][bk][bnq * 8]),
             Bt + (size_t)(k0 + bk) * LDB + bn + bnq * 8);
        cp16(smem_u32(&Bs[buf][bk + 16][bnq * 8]),
             Bt + (size_t)(k0 + bk + 16) * LDB + bn + bnq * 8);
        asm volatile("cp.async.commit_group;\n");
    };

    constexpr int KT = K / BK;
    load_async(0, 0);
    load_async(1, 1);

    for (int kt = 0; kt < KT; kt++) {
        if (kt + 1 < KT) asm volatile("cp.async.wait_group 1;\n");
        else             asm volatile("cp.async.wait_group 0;\n");
        __syncthreads();
        if (kt + 2 < KT) load_async(kt + 2, (kt + 2) % 3);
        const int buf = kt % 3;

#pragma unroll
        for (int kk = 0; kk < 2; kk++) {
            uint32_t af[4][4], bf[4][2];
#pragma unroll
            for (int im = 0; im < 4; im++) {
                uint32_t addr = smem_u32(
                    &As[buf][wm * 64 + im * 16 + (lane & 15)][kk * 16 + (lane >> 4) * 8]);
                asm volatile("ldmatrix.sync.aligned.m8n8.x4.shared.b16 {%0,%1,%2,%3}, [%4];\n"
                             : "=r"(af[im][0]), "=r"(af[im][1]), "=r"(af[im][2]), "=r"(af[im][3])
                             : "r"(addr));
            }
#pragma unroll
            for (int in = 0; in < 4; in++) {
                uint32_t addr = smem_u32(&Bs[buf][kk * 16 + (lane & 15)][wn * 32 + in * 8]);
                asm volatile("ldmatrix.sync.aligned.m8n8.x2.trans.shared.b16 {%0,%1}, [%2];\n"
                             : "=r"(bf[in][0]), "=r"(bf[in][1])
                             : "r"(addr));
            }
#pragma unroll
            for (int im = 0; im < 4; im++)
#pragma unroll
                for (int in = 0; in < 4; in++)
                    asm volatile("mma.sync.aligned.m16n8k16.row.col.f32.f16.f16.f32 "
                                 "{%0,%1,%2,%3}, {%4,%5,%6,%7}, {%8,%9}, {%0,%1,%2,%3};\n"
                                 : "+f"(acc[im][in][0]), "+f"(acc[im][in][1]),
                                   "+f"(acc[im][in][2]), "+f"(acc[im][in][3])
                                 : "r"(af[im][0]), "r"(af[im][1]), "r"(af[im][2]), "r"(af[im][3]),
                                   "r"(bf[in][0]), "r"(bf[in][1]));
        }
    }
}

// ---------------- per-step GATES kernel (256 CTAs = ONE wave at occ 2) ----------------
// gates_t from Xcat[t&1]; LSTM epilogue -> Xcat[(t+1)&1] h-part, g_c, g_Hall[t].
// bx==0 tiles also write x_{t+1}.
__global__ __launch_bounds__(256, 2) void gates_step(int t) {
    extern __shared__ char dynsmem[];
    const int blk = blockIdx.x;
    const int tid = threadIdx.x;
    const int by = blk >> 4, bx = blk & 15;
    const int bm = by * BM;
    const int bn = bx * BN;

    const __half* Ain = g_Xcat[t & 1];
    __half* Xout      = g_Xcat[(t + 1) & 1];

    float acc[4][4][4];
    gemm_mainloop<KA, KA, NF>(Ain, g_WfT, bm, bn, acc, dynsmem);

    const int lane = tid & 31;
    const int warp = tid >> 5;
    const int wm   = warp & 1;
    const int wn   = warp >> 1;

    // ---- LSTM epilogue, staged through smem for coalesced gmem ----
    float*  sC = (float*)dynsmem;                     // [128][36] c in/out
    __half* sH = (__half*)(dynsmem + 128 * 36 * 4);   // [128][40] h2
    const int d0 = bn >> 2;                           // 32 consecutive d

    __syncthreads();   // mainloop done; reuse smem
    // phase 1: coalesced c tile load
#pragma unroll
    for (int k = 0; k < 4; k++) {
        int idx = tid + k * 256;          // 0..1023 float4 chunks
        int row = idx >> 3, q = idx & 7;
        ((float4*)sC)[row * 9 + q] =
            *(const float4*)(g_c + (size_t)(bm + row) * DN + d0 + q * 4);
    }
    __syncthreads();

    // phase 2: gates -> (c2, h2) into smem
    const int pair_sel = lane & 1;
#pragma unroll
    for (int im = 0; im < 4; im++) {
        const int rl = wm * 64 + im * 16 + (lane >> 2);
#pragma unroll
        for (int in = 0; in < 4; in++) {
            const int ccg = bn + wn * 32 + in * 8 + (lane & 3) * 2;
            float b0 = __ldg(&g_gb[ccg]);
            float b1 = __ldg(&g_gb[ccg + 1]);
            float a0 = acc[im][in][0] + b0;
            float a1 = acc[im][in][1] + b1;
            float a2 = acc[im][in][2] + b0;
            float a3 = acc[im][in][3] + b1;
            float o0 = __shfl_xor_sync(0xffffffffu, a0, 1);
            float o1 = __shfl_xor_sync(0xffffffffu, a1, 1);
            float o2 = __shfl_xor_sync(0xffffffffu, a2, 1);
            float o3 = __shfl_xor_sync(0xffffffffu, a3, 1);
            int row_l; float xi, xf, xg, xo;
            if (pair_sel == 0) { row_l = rl;     xi = a0; xf = a1; xg = o0; xo = o1; }
            else               { row_l = rl + 8; xi = o2; xf = o3; xg = a2; xo = a3; }
            const int d_l = wn * 8 + in * 2 + ((lane & 3) >> 1);
            float si = 1.f / (1.f + expf(-xi));
            float sf = 1.f / (1.f + expf(-xf));
            float so = 1.f / (1.f + expf(-xo));
            float c2 = sf * sC[row_l * 36 + d_l] + si * tanhf(xg);
            float h2 = so * tanhf(c2);
            sC[row_l * 36 + d_l] = c2;
            sH[row_l * 40 + d_l] = __float2half(h2);
        }
    }
    __syncthreads();

    // phase 3: coalesced stores (c float4, h uint4 = 8 halves -> Xcat AND Hall)
#pragma unroll
    for (int k = 0; k < 4; k++) {
        int idx = tid + k * 256;
        int row = idx >> 3, q = idx & 7;
        *(float4*)(g_c + (size_t)(bm + row) * DN + d0 + q * 4) =
            ((const float4*)sC)[row * 9 + q];
    }
#pragma unroll
    for (int k = 0; k < 2; k++) {
        int idx = tid + k * 256;          // 0..511 uint4 chunks
        int row = idx >> 2, q = idx & 3;
        uint4 v = ((const uint4*)sH)[row * 5 + q];
        *(uint4*)(Xout + (size_t)(bm + row) * KA + d0 + q * 8) = v;
        *(uint4*)(g_Hall + ((size_t)t * BATCH + bm + row) * DN + d0 + q * 8) = v;
    }
    // bx==0 tile of each band writes x_{t+1}
    if (bx == 0) {
        const int rr = bm + (tid >> 1);
        const int jb = (tid & 1) * 16;
#pragma unroll
        for (int j = 0; j < 16; j++) {
            int jj = jb + j;
            Xout[(size_t)rr * KA + DN + jj] =
                __float2half(g_seq[(size_t)rr * SEQLEN + t + 1 + jj]);
        }
    }
}

// ---------------- bulk pu GEMM: Pall[TN*B, 768] = Hall[TN*B, 512] x Wpu ----------------
// Reuses g_WfT cols [2048, 2816) (k >= 512 rows are zero there; dropping them leaves
// fp32 results bit-identical since adding exact zeros is a no-op).
__global__ __launch_bounds__(256, 2) void pu_bulk() {
    extern __shared__ char dynsmem[];
    float acc[4][4][4];
    const int bm = blockIdx.y * BM;                 // 0..1023 bands of 128 rows
    const int bn = N4D + blockIdx.x * BN;           // pu cols
    gemm_mainloop<DN, DN, NF>(g_Hall, g_WfT, bm, bn, acc, dynsmem);

    const int tid  = threadIdx.x;
    const int lane = tid & 31;
    const int warp = tid >> 5;
    const int wm   = warp & 1;
    const int wn   = warp >> 1;
#pragma unroll
    for (int im = 0; im < 4; im++) {
        const int r = bm + wm * 64 + im * 16 + (lane >> 2);
#pragma unroll
        for (int in = 0; in < 4; in++) {
            const int cc = (bn - N4D) + wn * 32 + in * 8 + (lane & 3) * 2;
            *(float2*)(g_Pall + (size_t)r * NB + cc) =
                make_float2(acc[im][in][0], acc[im][in][1]);
            *(float2*)(g_Pall + (size_t)(r + 8) * NB + cc) =
                make_float2(acc[im][in][2], acc[im][in][3]);
        }
    }
}

// ---------------- deferred attention: all 64 steps, enc loaded ONCE ----------------
__global__ __launch_bounds__(256) void attn_all(
    const float* __restrict__ b_wp, const float* __restrict__ W_vp,
    const float* __restrict__ b_vp, const float* __restrict__ W_fc,
    const float* __restrict__ b_fc,
    float* __restrict__ outPred, float* __restrict__ outAlpha)
{
    const int b  = blockIdx.x;
    const int tid = threadIdx.x;

    __shared__ __align__(16) __half sEnc[SN * EN2];   // 33.8 KB
    __shared__ float sBwp[DN];
    __shared__ float sWvp[DN];
    __shared__ float sWfc[NB];
    __shared__ float sU[EN];
    __shared__ float sAtt[SN];
    __shared__ float sAlpha[SN];
    __shared__ float sRed[8];
    __shared__ float sAligned;

    const uint4* ge = (const uint4*)(g_enc + (size_t)b * SN * EN);
#pragma unroll
    for (int i = 0; i < 8; i++) {
        int c = tid + i * 256;
        int row = c >> 5, jc = c & 31;
        cp16(smem_u32(sEnc + row * EN2 + jc * 8), ge + c);
    }
    asm volatile("cp.async.commit_group;\n");

    sBwp[tid] = b_wp[tid];       sBwp[tid + 256] = b_wp[tid + 256];
    sWvp[tid] = W_vp[tid];       sWvp[tid + 256] = W_vp[tid + 256];
    sWfc[tid] = W_fc[tid];       sWfc[tid + 256] = W_fc[tid + 256];
    sWfc[tid + 512] = W_fc[tid + 512];
    const float bvp0 = b_vp[0];
    const float bfc0 = b_fc[0];

    asm volatile("cp.async.wait_group 0;\n");
    __syncthreads();

    for (int tt = 0; tt < TN; tt++) {
        const float*  Pr = g_Pall + ((size_t)tt * BATCH + b) * NB;
        const __half* hr = g_Hall + ((size_t)tt * BATCH + b) * DN;

        sU[tid] = Pr[DN + tid];

        float part = tanhf(Pr[tid] + sBwp[tid]) * sWvp[tid]
                   + tanhf(Pr[tid + 256] + sBwp[tid + 256]) * sWvp[tid + 256];
#pragma unroll
        for (int o = 16; o; o >>= 1) part += __shfl_xor_sync(0xffffffffu, part, o);
        if ((tid & 31) == 0) sRed[tid >> 5] = part;
        __syncthreads();
        if (tid == 0) {
            float tot = 0.f;
#pragma unroll
            for (int i = 0; i < 8; i++) tot += sRed[i];
            tot += bvp0;
            sAligned = (float)SN / (1.f + expf(-tot));
        }
        __syncthreads();
        const float aligned = sAligned;

        {
            int s = tid >> 2, q = tid & 3;
            const __half* er = sEnc + s * EN2;
            float a = 0.f;
#pragma unroll 16
            for (int e = q; e < EN; e += 4) a += __half2float(er[e]) * sU[e];
            a += __shfl_xor_sync(0xffffffffu, a, 1);
            a += __shfl_xor_sync(0xffffffffu, a, 2);
            if (q == 0) sAtt[s] = a;
        }
        __syncthreads();

        if (tid < 32) {
            float a0 = sAtt[tid], a1 = sAtt[tid + 32];
            float m = fmaxf(a0, a1);
#pragma unroll
            for (int o = 16; o; o >>= 1) m = fmaxf(m, __shfl_xor_sync(0xffffffffu, m, o));
            float e0 = expf(a0 - m), e1 = expf(a1 - m);
            float s2 = e0 + e1;
#pragma unroll
            for (int o = 16; o; o >>= 1) s2 += __shfl_xor_sync(0xffffffffu, s2, o);
            float inv = 1.f / s2;
            float d0 = (float)tid - aligned, d1 = (float)(tid + 32) - aligned;
            sAlpha[tid]      = e0 * inv * expf(-0.5f * d0 * d0);
            sAlpha[tid + 32] = e1 * inv * expf(-0.5f * d1 * d1);
        }
        __syncthreads();

        if (tid < SN)
            outAlpha[((size_t)b * TN + tt) * SN + tid] = sAlpha[tid];

        float awe = 0.f;
#pragma unroll 16
        for (int s = 0; s < SN; s++) awe += __half2float(sEnc[s * EN2 + tid]) * sAlpha[s];

        float pp = awe * sWfc[tid]
                 + __half2float(hr[tid])       * sWfc[EN + tid]
                 + __half2float(hr[tid + 256]) * sWfc[EN + 256 + tid];
#pragma unroll
        for (int o = 16; o; o >>= 1) pp += __shfl_xor_sync(0xffffffffu, pp, o);
        if ((tid & 31) == 0) sRed[tid >> 5] = pp;
        __syncthreads();
        if (tid == 0) {
            float tot = 0.f;
#pragma unroll
            for (int i = 0; i < 8; i++) tot += sRed[i];
            outPred[(size_t)b * TN + tt] = tot + bfc0;
        }
        __syncthreads();
    }
}

// ---------------- init GEMM (h0|c0) ----------------
__global__ __launch_bounds__(256, 2) void gemmI_kernel() {
    extern __shared__ char dynsmem[];
    float acc[4][4][4];
    const int bm = blockIdx.y * BM;
    const int bn = blockIdx.x * BN;
    gemm_mainloop<288, 288, 1024>(g_Inp, g_WiT, bm, bn, acc, dynsmem);
    const int tid  = threadIdx.x;
    const int lane = tid & 31;
    const int warp = tid >> 5;
    const int wm   = warp & 1;
    const int wn   = warp >> 1;
#pragma unroll
    for (int im = 0; im < 4; im++) {
        const int r = bm + wm * 64 + im * 16 + (lane >> 2);
#pragma unroll
        for (int in = 0; in < 4; in++) {
            const int cc = bn + wn * 32 + in * 8 + (lane & 3) * 2;
            *(float2*)(g_gates + (size_t)r * 1024 + cc) =
                make_float2(acc[im][in][0], acc[im][in][1]);
            *(float2*)(g_gates + (size_t)(r + 8) * 1024 + cc) =
                make_float2(acc[im][in][2], acc[im][in][3]);
        }
    }
}

// ---------------- merged init / pack kernels ----------------
__global__ void prep1(const float* __restrict__ encSrc,
                      const float* __restrict__ hist, const float* __restrict__ cur) {
    size_t i = (size_t)blockIdx.x * 256 + threadIdx.x;
    const size_t n4 = (size_t)BATCH * SN * EN / 4;
    if (i < n4) {
        float4 v = ((const float4*)encSrc)[i];
        __half2* dst = (__half2*)g_enc;
        dst[2 * i]     = __floats2half2_rn(v.x, v.y);
        dst[2 * i + 1] = __floats2half2_rn(v.z, v.w);
    }
    if (i < (size_t)BATCH * SEQLEN) {
        int b = (int)(i / SEQLEN), j = (int)(i - (size_t)b * SEQLEN);
        float v = (j < 31) ? hist[(size_t)b * 31 + j]
                : (j < 95) ? cur[(size_t)b * TN + (j - 31)] : 0.f;
        g_seq[i] = v;
    }
}
__global__ void prep2(const float* __restrict__ W_hh, const float* __restrict__ W_ih,
                      const float* __restrict__ W_wp, const float* __restrict__ W_wa,
                      const float* __restrict__ b_ih, const float* __restrict__ b_hh,
                      const float* __restrict__ W_init_h, const float* __restrict__ W_init_c) {
    int idx = blockIdx.x * 256 + threadIdx.x;
    if (idx < N4D) {
        int d = idx >> 2, g = idx & 3;
        g_gb[idx] = b_ih[g * DN + d] + b_hh[g * DN + d];
    }
    if (idx < 288 * 1024) {
        int k = idx / 1024, n = idx - k * 1024;
        float v = (n < DN) ? W_init_h[(size_t)n * 288 + k]
                           : W_init_c[(size_t)(n - DN) * 288 + k];
        g_WiT[idx] = __float2half(v);
    }
    if (idx >= KA * NF) return;
    int k = idx / NF, n = idx - k * NF;
    float v;
    if (n < N4D) {
        int d = n >> 2, g = n & 3;
        int gr = g * DN + d;
        v = (k < DN) ? W_hh[(size_t)gr * DN + k] : W_ih[(size_t)gr * INN + (k - DN)];
    } else if (n < N4D + DN) {
        int d = n - N4D;
        v = (k < DN) ? W_wp[(size_t)d * DN + k] : 0.f;
    } else {
        int e = n - N4D - DN;
        v = (k < DN) ? W_wa[(size_t)k * EN + e] : 0.f;
    }
    g_WfT[idx] = __float2half(v);
}
__global__ void mean_inp(const float* __restrict__ cEnc) {
    int b = blockIdx.x, tid = threadIdx.x;
    const float* p = cEnc + (size_t)b * SN * EN + tid;
    float s = 0.f;
#pragma unroll 8
    for (int i = 0; i < SN; i++) s += p[(size_t)i * EN];
    g_Inp[(size_t)b * 288 + tid] = __float2half(s * (1.f / 64.f));
    if (tid < INN)
        g_Inp[(size_t)b * 288 + EN + tid] = __float2half(g_seq[(size_t)b * SEQLEN + tid]);
}
__global__ void init_finish(const float* __restrict__ b_init_h, const float* __restrict__ b_init_c) {
    int idx = blockIdx.x * 256 + threadIdx.x;
    if (idx >= BATCH * KA) return;
    int b = idx / KA, d = idx - b * KA;
    if (d < DN) {
        float h0 = g_gates[(size_t)b * 1024 + d] + b_init_h[d];
        float c0 = g_gates[(size_t)b * 1024 + DN + d] + b_init_c[d];
        g_c[(size_t)b * DN + d] = c0;
        g_Xcat[0][idx] = __float2half(h0);
    } else {
        g_Xcat[0][idx] = __float2half(g_seq[(size_t)b * SEQLEN + (d - DN)]);  // x_0
    }
}

// ---------------- launcher (single stream, graph-capturable) ----------------
extern "C" void kernel_launch(void* const* d_in, const int* in_sizes, int n_in,
                              void* d_out, int out_size) {
    const float* cEnc       = (const float*)d_in[0];
    const float* curSpeeds  = (const float*)d_in[1];
    const float* histSpeeds = (const float*)d_in[2];
    int wo = (n_in > 5 && in_sizes[5] == 1) ? 6 : 5;
    const float* W_init_h = (const float*)d_in[wo + 0];
    const float* b_init_h = (const float*)d_in[wo + 1];
    const float* W_init_c = (const float*)d_in[wo + 2];
    const float* b_init_c = (const float*)d_in[wo + 3];
    const float* W_ih     = (const float*)d_in[wo + 4];
    const float* W_hh     = (const float*)d_in[wo + 5];
    const float* b_ih     = (const float*)d_in[wo + 6];
    const float* b_hh     = (const float*)d_in[wo + 7];
    const float* W_wa     = (const float*)d_in[wo + 8];
    // b_wa (wo+9) is softmax-invariant: unused
    const float* W_wp     = (const float*)d_in[wo + 10];
    const float* b_wp     = (const float*)d_in[wo + 11];
    const float* W_vp     = (const float*)d_in[wo + 12];
    const float* b_vp     = (const float*)d_in[wo + 13];
    const float* W_fc     = (const float*)d_in[wo + 14];
    const float* b_fc     = (const float*)d_in[wo + 15];

    float* outPred  = (float*)d_out;                 // [B,T,1]
    float* outAlpha = outPred + (size_t)BATCH * TN;  // [B,T,S]

    cudaFuncSetAttribute(gates_step, cudaFuncAttributeMaxDynamicSharedMemorySize, DYN_I);
    cudaFuncSetAttribute(pu_bulk,    cudaFuncAttributeMaxDynamicSharedMemorySize, DYN_I);
    cudaFuncSetAttribute(gemmI_kernel, cudaFuncAttributeMaxDynamicSharedMemorySize, DYN_I);

    prep1<<<32768, 256>>>(cEnc, histSpeeds, curSpeeds);
    prep2<<<(KA * NF + 255) / 256, 256>>>(W_hh, W_ih, W_wp, W_wa,
                                          b_ih, b_hh, W_init_h, W_init_c);
    mean_inp<<<BATCH, 256>>>(cEnc);
    gemmI_kernel<<<dim3(1024 / BN, BATCH / BM), 256, DYN_I>>>();
    init_finish<<<(BATCH * KA) / 256, 256>>>(b_init_h, b_init_c);

    // recurrence: 64 gates-only launches, 256 CTAs each = ONE resident wave
    for (int t = 0; t < TN; t++)
        gates_step<<<256, 256, DYN_I>>>(t);

    // all pu projections as one bulk GEMM (6144 CTAs, throughput-bound)
    pu_bulk<<<dim3(NB / BN, (TN * BATCH) / BM), 256, DYN_I>>>();

    // all 64 attention steps in one pass (enc loaded once per batch)
    attn_all<<<BATCH, 256>>>(b_wp, W_vp, b_vp, W_fc, b_fc, outPred, outAlpha);
}